// round 1
// baseline (speedup 1.0000x reference)
#include <cuda_runtime.h>
#include <cuda_bf16.h>
#include <math.h>

// CGCNN on GB300. Structure per layer:
//   T_src[n][0:64]=h@gw_rows0..63, [64:128]=h@cw_rows0..63
//   T_dst[n][0:64]=h@gw_rows64..127+gb, [64:128]=h@cw_rows64..127+cb
//   per edge e=(s,d): g=sigmoid(Ts[s].g+Td[d].g+e@gwE), c=softplus(Ts[s].c+Td[d].c+e@cwE)
//   agg[s] += g*c (vector f32 atomics); BN(batch stats); h=softplus(h+BN(agg))
// Then mean-pool per graph + 3-layer MLP.

#define NN 100000
#define EE 1600000
#define BB 256
#define HH 64
#define FN 35
#define FE 10

__device__ float g_h[NN * 64];
__device__ float g_Ts[NN * 128];
__device__ float g_Td[NN * 128];
__device__ float g_agg[NN * 64];
__device__ float g_stats[128];
__device__ float g_scale[64];
__device__ float g_shift[64];
__device__ float g_pool[BB * 64];
__device__ float g_cnt[BB];

__device__ __forceinline__ float fsoftplus(float x) {
    return fmaxf(x, 0.f) + __logf(1.f + __expf(-fabsf(x)));
}
__device__ __forceinline__ float fsigmoid(float x) {
    return __fdividef(1.f, 1.f + __expf(-x));
}
__device__ __forceinline__ void red_add_v4(float* p, float a, float b, float c, float d) {
    asm volatile("red.global.add.v4.f32 [%0], {%1, %2, %3, %4};"
                 :: "l"(p), "f"(a), "f"(b), "f"(c), "f"(d) : "memory");
}
__device__ __forceinline__ void red_add_f(float* p, float v) {
    asm volatile("red.global.add.f32 [%0], %1;" :: "l"(p), "f"(v) : "memory");
}

// ---------------- embed: h = nf @ ew + eb ----------------
__global__ void embed_k(const float* __restrict__ nf, const float* __restrict__ ew,
                        const float* __restrict__ eb) {
    __shared__ float sw[FN * 64];
    __shared__ float sb[64];
    __shared__ float snf[4][FN];
    int tid = threadIdx.x;
    for (int i = tid; i < FN * 64; i += 256) sw[i] = ew[i];
    if (tid < 64) sb[tid] = eb[tid];
    int n0 = blockIdx.x * 4;
    for (int i = tid; i < 4 * FN; i += 256) {
        int r = i / FN, c = i % FN;
        int n = n0 + r;
        snf[r][c] = (n < NN) ? nf[n * FN + c] : 0.f;
    }
    __syncthreads();
    int r = tid >> 6, j = tid & 63;
    int n = n0 + r;
    if (n < NN) {
        float acc = sb[j];
#pragma unroll
        for (int k = 0; k < FN; k++) acc = fmaf(snf[r][k], sw[k * 64 + j], acc);
        g_h[n * 64 + j] = acc;
    }
}

// ---------------- node transform: 64 nodes x 256 cols per block ----------------
// smem: ws[64][256] combined weight, hs[64][68] padded h tile
#define NT_SMEM ((64 * 256 + 64 * 68) * 4)
__global__ __launch_bounds__(256, 2) void nodetf_k(
    const float* __restrict__ gw, const float* __restrict__ cw,
    const float* __restrict__ gb, const float* __restrict__ cb) {
    extern __shared__ float sm[];
    float* ws = sm;             // [64][256]
    float* hs = sm + 64 * 256;  // [64][68]
    __shared__ float bias[128];
    int tid = threadIdx.x;
    for (int i = tid; i < 64 * 256; i += 256) {
        int k = i >> 8, c = i & 255;
        float v;
        if (c < 64)       v = gw[k * 64 + c];
        else if (c < 128) v = cw[k * 64 + (c - 64)];
        else if (c < 192) v = gw[(64 + k) * 64 + (c - 128)];
        else              v = cw[(64 + k) * 64 + (c - 192)];
        ws[i] = v;
    }
    if (tid < 64) bias[tid] = gb[tid];
    else if (tid < 128) bias[tid] = cb[tid - 64];
    int n0 = blockIdx.x * 64;
    for (int i = tid; i < 64 * 64; i += 256) {
        int r = i >> 6, c = i & 63;
        int n = n0 + r;
        hs[r * 68 + c] = (n < NN) ? g_h[n * 64 + c] : 0.f;
    }
    __syncthreads();

    int cg = tid & 7;        // column group: cols [32*cg, 32*cg+32)
    int ng = tid >> 3;       // node group: nodes 2*ng, 2*ng+1
    int cbase = cg * 32;
    int na = 2 * ng, nb = na + 1;
    float acc0[32], acc1[32];
#pragma unroll
    for (int i = 0; i < 32; i++) { acc0[i] = 0.f; acc1[i] = 0.f; }

    for (int k = 0; k < 64; k++) {
        float ha = hs[na * 68 + k];
        float hb = hs[nb * 68 + k];
        const float4* wr = (const float4*)(ws + k * 256 + cbase);
#pragma unroll
        for (int q = 0; q < 8; q++) {
            float4 w = wr[q];
            acc0[4 * q + 0] = fmaf(ha, w.x, acc0[4 * q + 0]);
            acc0[4 * q + 1] = fmaf(ha, w.y, acc0[4 * q + 1]);
            acc0[4 * q + 2] = fmaf(ha, w.z, acc0[4 * q + 2]);
            acc0[4 * q + 3] = fmaf(ha, w.w, acc0[4 * q + 3]);
            acc1[4 * q + 0] = fmaf(hb, w.x, acc1[4 * q + 0]);
            acc1[4 * q + 1] = fmaf(hb, w.y, acc1[4 * q + 1]);
            acc1[4 * q + 2] = fmaf(hb, w.z, acc1[4 * q + 2]);
            acc1[4 * q + 3] = fmaf(hb, w.w, acc1[4 * q + 3]);
        }
    }

    bool isSrc = (cbase < 128);
    int coff = isSrc ? cbase : (cbase - 128);
    int nA = n0 + na, nB = n0 + nb;
    if (nA < NN) {
        float* dst = isSrc ? (g_Ts + nA * 128 + coff) : (g_Td + nA * 128 + coff);
#pragma unroll
        for (int q = 0; q < 8; q++) {
            float b0 = isSrc ? 0.f : bias[coff + 4 * q + 0];
            float b1 = isSrc ? 0.f : bias[coff + 4 * q + 1];
            float b2 = isSrc ? 0.f : bias[coff + 4 * q + 2];
            float b3 = isSrc ? 0.f : bias[coff + 4 * q + 3];
            ((float4*)dst)[q] = make_float4(acc0[4 * q + 0] + b0, acc0[4 * q + 1] + b1,
                                            acc0[4 * q + 2] + b2, acc0[4 * q + 3] + b3);
        }
    }
    if (nB < NN) {
        float* dst = isSrc ? (g_Ts + nB * 128 + coff) : (g_Td + nB * 128 + coff);
#pragma unroll
        for (int q = 0; q < 8; q++) {
            float b0 = isSrc ? 0.f : bias[coff + 4 * q + 0];
            float b1 = isSrc ? 0.f : bias[coff + 4 * q + 1];
            float b2 = isSrc ? 0.f : bias[coff + 4 * q + 2];
            float b3 = isSrc ? 0.f : bias[coff + 4 * q + 3];
            ((float4*)dst)[q] = make_float4(acc1[4 * q + 0] + b0, acc1[4 * q + 1] + b1,
                                            acc1[4 * q + 2] + b2, acc1[4 * q + 3] + b3);
        }
    }
}

// ---------------- zero kernels ----------------
__global__ void zero_agg_k() {
    int i = blockIdx.x * 256 + threadIdx.x;
    if (i < NN * 16) ((float4*)g_agg)[i] = make_float4(0.f, 0.f, 0.f, 0.f);
    if (i < 128) g_stats[i] = 0.f;
}
__global__ void zero_pool_k() {
    int i = blockIdx.x * 256 + threadIdx.x;
    if (i < BB * 64) g_pool[i] = 0.f;
    if (i < BB) g_cnt[i] = 0.f;
}

// ---------------- edge pass ----------------
// 256 threads = 16 half-warps, half-warp handles one edge (4 feats/lane), 8 iters
__global__ __launch_bounds__(256) void edge_k(
    const int* __restrict__ src, const int* __restrict__ dst,
    const float* __restrict__ ef,
    const float* __restrict__ gwE, const float* __restrict__ cwE) {
    __shared__ float sg[FE * 64];
    __shared__ float sc[FE * 64];
    int tid = threadIdx.x;
    for (int i = tid; i < FE * 64; i += 256) { sg[i] = gwE[i]; sc[i] = cwE[i]; }
    __syncthreads();
    int half = tid >> 4;   // 0..15
    int l = tid & 15;      // lane within half-warp

#pragma unroll 1
    for (int it = 0; it < 8; it++) {
        int e = blockIdx.x * 128 + it * 16 + half;
        if (e >= EE) continue;
        int s = src[e];
        int d = dst[e];
        const float4* ts = (const float4*)(g_Ts + (size_t)s * 128);
        const float4* td = (const float4*)(g_Td + (size_t)d * 128);
        float4 gA = ts[l];
        float4 cA = ts[16 + l];
        float4 gB = td[l];
        float4 cB = td[16 + l];
        float x0 = gA.x + gB.x, x1 = gA.y + gB.y, x2 = gA.z + gB.z, x3 = gA.w + gB.w;
        float y0 = cA.x + cB.x, y1 = cA.y + cB.y, y2 = cA.z + cB.z, y3 = cA.w + cB.w;

        float evl = (l < FE) ? ef[(size_t)e * FE + l] : 0.f;
#pragma unroll
        for (int k = 0; k < FE; k++) {
            float ev = __shfl_sync(0xffffffffu, evl, k, 16);
            float4 wg = *(const float4*)(sg + k * 64 + 4 * l);
            float4 wc = *(const float4*)(sc + k * 64 + 4 * l);
            x0 = fmaf(ev, wg.x, x0); x1 = fmaf(ev, wg.y, x1);
            x2 = fmaf(ev, wg.z, x2); x3 = fmaf(ev, wg.w, x3);
            y0 = fmaf(ev, wc.x, y0); y1 = fmaf(ev, wc.y, y1);
            y2 = fmaf(ev, wc.z, y2); y3 = fmaf(ev, wc.w, y3);
        }
        float m0 = fsigmoid(x0) * fsoftplus(y0);
        float m1 = fsigmoid(x1) * fsoftplus(y1);
        float m2 = fsigmoid(x2) * fsoftplus(y2);
        float m3 = fsigmoid(x3) * fsoftplus(y3);
        red_add_v4(g_agg + (size_t)s * 64 + 4 * l, m0, m1, m2, m3);
    }
}

// ---------------- BN stats ----------------
__global__ void stats_k() {
    int tid = threadIdx.x;
    int j = tid & 63;
    int r = tid >> 6;  // 0..3
    float s = 0.f, s2 = 0.f;
    for (int n = blockIdx.x * 4 + r; n < NN; n += gridDim.x * 4) {
        float v = g_agg[n * 64 + j];
        s += v;
        s2 += v * v;
    }
    __shared__ float sh[256], sh2[256];
    sh[tid] = s; sh2[tid] = s2;
    __syncthreads();
    if (tid < 64) {
        s = sh[tid] + sh[tid + 64] + sh[tid + 128] + sh[tid + 192];
        s2 = sh2[tid] + sh2[tid + 64] + sh2[tid + 128] + sh2[tid + 192];
        atomicAdd(&g_stats[tid], s);
        atomicAdd(&g_stats[64 + tid], s2);
    }
}

__global__ void bnfin_k(const float* __restrict__ bg, const float* __restrict__ bb) {
    int j = threadIdx.x;
    float mean = g_stats[j] * (1.f / NN);
    float var = g_stats[64 + j] * (1.f / NN) - mean * mean;
    float sc = bg[j] * rsqrtf(fmaxf(var, 0.f) + 1e-5f);
    g_scale[j] = sc;
    g_shift[j] = bb[j] - mean * sc;
}

// ---------------- h = softplus(h + agg*scale + shift) ----------------
__global__ void upd_k() {
    int i = blockIdx.x * 256 + threadIdx.x;
    if (i >= NN * 16) return;
    int j4 = (i & 15) * 4;
    float4 a = ((const float4*)g_agg)[i];
    float4 h = ((const float4*)g_h)[i];
    float4 sc = *(const float4*)(g_scale + j4);
    float4 sf = *(const float4*)(g_shift + j4);
    h.x = fsoftplus(fmaf(a.x, sc.x, h.x + sf.x));
    h.y = fsoftplus(fmaf(a.y, sc.y, h.y + sf.y));
    h.z = fsoftplus(fmaf(a.z, sc.z, h.z + sf.z));
    h.w = fsoftplus(fmaf(a.w, sc.w, h.w + sf.w));
    ((float4*)g_h)[i] = h;
}

// ---------------- pooling ----------------
__global__ void pool_k(const int* __restrict__ gi) {
    int i = blockIdx.x * 256 + threadIdx.x;
    if (i >= NN * 16) return;
    int n = i >> 4;
    int q = i & 15;
    int g = gi[n];
    float4 v = ((const float4*)g_h)[i];
    red_add_v4(g_pool + g * 64 + 4 * q, v.x, v.y, v.z, v.w);
    if (q == 0) red_add_f(&g_cnt[g], 1.f);
}

// ---------------- final MLP, one block per graph ----------------
__global__ void mlp_k(const float* __restrict__ w1, const float* __restrict__ b1,
                      const float* __restrict__ w2, const float* __restrict__ b2,
                      const float* __restrict__ w3, const float* __restrict__ b3,
                      float* __restrict__ out) {
    int b = blockIdx.x;
    int t = threadIdx.x;  // 128 threads
    __shared__ float pm[64];
    __shared__ float s1[128];
    __shared__ float s2[64];
    __shared__ float red[128];
    if (t < 64) {
        float c = g_cnt[b];
        c = (c < 1.f) ? 1.f : c;
        pm[t] = g_pool[b * 64 + t] / c;
    }
    __syncthreads();
    float a = b1[t];
#pragma unroll
    for (int k = 0; k < 64; k++) a = fmaf(pm[k], w1[k * 128 + t], a);
    s1[t] = fsoftplus(a);
    __syncthreads();
    if (t < 64) {
        float a2 = b2[t];
#pragma unroll
        for (int k = 0; k < 128; k++) a2 = fmaf(s1[k], w2[k * 64 + t], a2);
        s2[t] = fsoftplus(a2);
    }
    __syncthreads();
    float p = (t < 64) ? s2[t] * w3[t] : 0.f;
    red[t] = p;
    __syncthreads();
#pragma unroll
    for (int off = 64; off > 0; off >>= 1) {
        if (t < off) red[t] += red[t + off];
        __syncthreads();
    }
    if (t == 0) out[b] = red[0] + b3[0];
}

extern "C" void kernel_launch(void* const* d_in, const int* in_sizes, int n_in,
                              void* d_out, int out_size) {
    const float* nf  = (const float*)d_in[0];
    const int*   ei  = (const int*)d_in[1];
    const float* ef  = (const float*)d_in[2];
    const int*   gi  = (const int*)d_in[3];
    const float* ew  = (const float*)d_in[4];
    const float* eb  = (const float*)d_in[5];
    const float* gw  = (const float*)d_in[6];
    const float* gb  = (const float*)d_in[7];
    const float* cw  = (const float*)d_in[8];
    const float* cb  = (const float*)d_in[9];
    const float* bng = (const float*)d_in[10];
    const float* bnb = (const float*)d_in[11];
    const float* w1  = (const float*)d_in[12];
    const float* b1  = (const float*)d_in[13];
    const float* w2  = (const float*)d_in[14];
    const float* b2  = (const float*)d_in[15];
    const float* w3  = (const float*)d_in[16];
    const float* b3  = (const float*)d_in[17];
    float* out = (float*)d_out;
    const int* srcI = ei;
    const int* dstI = ei + EE;

    cudaFuncSetAttribute(nodetf_k, cudaFuncAttributeMaxDynamicSharedMemorySize, NT_SMEM);

    embed_k<<<(NN + 3) / 4, 256>>>(nf, ew, eb);
    for (int i = 0; i < 3; i++) {
        const float* gwi = gw + i * 138 * 64;
        const float* cwi = cw + i * 138 * 64;
        nodetf_k<<<(NN + 63) / 64, 256, NT_SMEM>>>(gwi, cwi, gb + i * 64, cb + i * 64);
        zero_agg_k<<<(NN * 16 + 255) / 256, 256>>>();
        edge_k<<<(EE + 127) / 128, 256>>>(srcI, dstI, ef, gwi + 128 * 64, cwi + 128 * 64);
        stats_k<<<512, 256>>>();
        bnfin_k<<<1, 64>>>(bng + i * 64, bnb + i * 64);
        upd_k<<<(NN * 16 + 255) / 256, 256>>>();
    }
    zero_pool_k<<<64, 256>>>();
    pool_k<<<(NN * 16 + 255) / 256, 256>>>(gi);
    mlp_k<<<BB, 128>>>(w1, b1, w2, b2, w3, b3, out);
}

// round 3
// speedup vs baseline: 3.4453x; 3.4453x over previous
#include <cuda_runtime.h>
#include <cuda_bf16.h>
#include <math.h>

// CGCNN on GB300.
//   T_src[n][0:64]=h@gw_rows0..63, [64:128]=h@cw_rows0..63
//   T_dst[n][0:64]=h@gw_rows64..127+gb, [64:128]=h@cw_rows64..127+cb
//   per edge e=(s,d): g=sigmoid(Ts[s].g+Td[d].g+e@gwE), c=softplus(Ts[s].c+Td[d].c+e@cwE)
//   agg[s] += g*c (vector f32 atomics); BN(batch stats); h=softplus(h+BN(agg))
// Then mean-pool per graph + 3-layer MLP.

#define NN 100000
#define EE 1600000
#define BB 256
#define HH 64
#define FN 35
#define FE 10

__device__ float g_h[NN * 64];
__device__ float g_Ts[NN * 128];
__device__ float g_Td[NN * 128];
__device__ float g_agg[NN * 64];
__device__ float g_stats[128];
__device__ float g_scale[64];
__device__ float g_shift[64];
__device__ float g_pool[BB * 64];
__device__ float g_cnt[BB];

__device__ __forceinline__ float fsoftplus(float x) {
    return fmaxf(x, 0.f) + __logf(1.f + __expf(-fabsf(x)));
}
__device__ __forceinline__ float fsigmoid(float x) {
    return __fdividef(1.f, 1.f + __expf(-x));
}
__device__ __forceinline__ void red_add_v4(float* p, float a, float b, float c, float d) {
    asm volatile("red.global.add.v4.f32 [%0], {%1, %2, %3, %4};"
                 :: "l"(p), "f"(a), "f"(b), "f"(c), "f"(d) : "memory");
}
__device__ __forceinline__ void red_add_f(float* p, float v) {
    asm volatile("red.global.add.f32 [%0], %1;" :: "l"(p), "f"(v) : "memory");
}

// ---------------- embed: h = nf @ ew + eb, 32 nodes/block ----------------
__global__ __launch_bounds__(256) void embed_k(const float* __restrict__ nf,
                                               const float* __restrict__ ew,
                                               const float* __restrict__ eb) {
    __shared__ float sw[FN * 64];
    __shared__ float sb[64];
    __shared__ float snf[32][FN + 1];
    int tid = threadIdx.x;
    for (int i = tid; i < FN * 64; i += 256) sw[i] = ew[i];
    if (tid < 64) sb[tid] = eb[tid];
    int n0 = blockIdx.x * 32;
    for (int i = tid; i < 32 * FN; i += 256) {
        int r = i / FN, c = i % FN;
        int n = n0 + r;
        snf[r][c] = (n < NN) ? nf[(size_t)n * FN + c] : 0.f;
    }
    __syncthreads();
    int r = tid >> 6, j = tid & 63;  // r in 0..3
#pragma unroll
    for (int ii = 0; ii < 8; ii++) {
        int rr = r + ii * 4;
        int n = n0 + rr;
        if (n < NN) {
            float acc = sb[j];
#pragma unroll
            for (int k = 0; k < FN; k++) acc = fmaf(snf[rr][k], sw[k * 64 + j], acc);
            g_h[(size_t)n * 64 + j] = acc;
        }
    }
}

// ---------------- node transform: register weights, broadcast h ----------------
// 256 threads, thread owns one output column c (0..255); 64-node tiles.
__global__ __launch_bounds__(256) void nodetf_k(
    const float* __restrict__ gw, const float* __restrict__ cw,
    const float* __restrict__ gb, const float* __restrict__ cb) {
    __shared__ float4 hs4[64 * 16];  // 64 nodes x 64 feats
    int c = threadIdx.x;
    const float* wp;
    int cc;
    float bias = 0.f;
    if (c < 64)       { wp = gw;           cc = c; }
    else if (c < 128) { wp = cw;           cc = c - 64; }
    else if (c < 192) { wp = gw + 64 * 64; cc = c - 128; bias = gb[cc]; }
    else              { wp = cw + 64 * 64; cc = c - 192; bias = cb[cc]; }
    float w[64];
#pragma unroll
    for (int k = 0; k < 64; k++) w[k] = wp[k * 64 + cc];

    float* outp = (c < 128) ? (g_Ts + c) : (g_Td + (c - 128));

    int n0 = blockIdx.x * 64;
    // load h tile: 1024 float4 by 256 threads = 4 iters (zero-pad tail)
#pragma unroll
    for (int i = 0; i < 4; i++) {
        int idx = c + i * 256;
        int n = n0 + (idx >> 4);
        hs4[idx] = (n < NN) ? ((const float4*)g_h)[(size_t)n0 * 16 + idx]
                            : make_float4(0.f, 0.f, 0.f, 0.f);
    }
    __syncthreads();

#pragma unroll 1
    for (int j0 = 0; j0 < 64; j0 += 8) {
        float acc[8];
#pragma unroll
        for (int j = 0; j < 8; j++) acc[j] = bias;
#pragma unroll
        for (int k4 = 0; k4 < 16; k4++) {
#pragma unroll
            for (int j = 0; j < 8; j++) {
                float4 h = hs4[(j0 + j) * 16 + k4];
                acc[j] = fmaf(h.x, w[4 * k4 + 0], acc[j]);
                acc[j] = fmaf(h.y, w[4 * k4 + 1], acc[j]);
                acc[j] = fmaf(h.z, w[4 * k4 + 2], acc[j]);
                acc[j] = fmaf(h.w, w[4 * k4 + 3], acc[j]);
            }
        }
#pragma unroll
        for (int j = 0; j < 8; j++) {
            int n = n0 + j0 + j;
            if (n < NN) outp[(size_t)n * 128] = acc[j];
        }
    }
}

// ---------------- zero kernels ----------------
__global__ void zero_agg_k() {
    int i = blockIdx.x * 256 + threadIdx.x;
    if (i < NN * 16) ((float4*)g_agg)[i] = make_float4(0.f, 0.f, 0.f, 0.f);
    if (i < 128) g_stats[i] = 0.f;
}
__global__ void zero_pool_k() {
    int i = blockIdx.x * 256 + threadIdx.x;
    if (i < BB * 64) g_pool[i] = 0.f;
    if (i < BB) g_cnt[i] = 0.f;
}

// ---------------- edge pass: weights in registers, 256 edges/block ----------------
#define EDGE_ITERS 16
__global__ __launch_bounds__(256) void edge_k(
    const int* __restrict__ src, const int* __restrict__ dst,
    const float* __restrict__ ef,
    const float* __restrict__ gwE, const float* __restrict__ cwE) {
    int tid = threadIdx.x;
    int half = tid >> 4;   // 0..15
    int l = tid & 15;      // lane within half-warp

    float4 wg[FE], wc[FE];
#pragma unroll
    for (int k = 0; k < FE; k++) {
        wg[k] = *(const float4*)(gwE + k * 64 + 4 * l);
        wc[k] = *(const float4*)(cwE + k * 64 + 4 * l);
    }

#pragma unroll 1
    for (int it = 0; it < EDGE_ITERS; it++) {
        int e = blockIdx.x * (16 * EDGE_ITERS) + it * 16 + half;
        if (e >= EE) continue;
        int s = src[e];
        int d = dst[e];
        const float4* ts = (const float4*)(g_Ts + (size_t)s * 128);
        const float4* td = (const float4*)(g_Td + (size_t)d * 128);
        float4 gA = ts[l];
        float4 cA = ts[16 + l];
        float4 gB = td[l];
        float4 cB = td[16 + l];
        float x0 = gA.x + gB.x, x1 = gA.y + gB.y, x2 = gA.z + gB.z, x3 = gA.w + gB.w;
        float y0 = cA.x + cB.x, y1 = cA.y + cB.y, y2 = cA.z + cB.z, y3 = cA.w + cB.w;

        float evl = (l < FE) ? ef[(size_t)e * FE + l] : 0.f;
#pragma unroll
        for (int k = 0; k < FE; k++) {
            float ev = __shfl_sync(0xffffffffu, evl, k, 16);
            x0 = fmaf(ev, wg[k].x, x0); x1 = fmaf(ev, wg[k].y, x1);
            x2 = fmaf(ev, wg[k].z, x2); x3 = fmaf(ev, wg[k].w, x3);
            y0 = fmaf(ev, wc[k].x, y0); y1 = fmaf(ev, wc[k].y, y1);
            y2 = fmaf(ev, wc[k].z, y2); y3 = fmaf(ev, wc[k].w, y3);
        }
        float m0 = fsigmoid(x0) * fsoftplus(y0);
        float m1 = fsigmoid(x1) * fsoftplus(y1);
        float m2 = fsigmoid(x2) * fsoftplus(y2);
        float m3 = fsigmoid(x3) * fsoftplus(y3);
        red_add_v4(g_agg + (size_t)s * 64 + 4 * l, m0, m1, m2, m3);
    }
}

// ---------------- BN stats ----------------
__global__ void stats_k() {
    int tid = threadIdx.x;
    int j = tid & 63;
    int r = tid >> 6;  // 0..3
    float s = 0.f, s2 = 0.f;
    for (int n = blockIdx.x * 4 + r; n < NN; n += gridDim.x * 4) {
        float v = g_agg[n * 64 + j];
        s += v;
        s2 += v * v;
    }
    __shared__ float sh[256], sh2[256];
    sh[tid] = s; sh2[tid] = s2;
    __syncthreads();
    if (tid < 64) {
        s = sh[tid] + sh[tid + 64] + sh[tid + 128] + sh[tid + 192];
        s2 = sh2[tid] + sh2[tid + 64] + sh2[tid + 128] + sh2[tid + 192];
        atomicAdd(&g_stats[tid], s);
        atomicAdd(&g_stats[64 + tid], s2);
    }
}

__global__ void bnfin_k(const float* __restrict__ bg, const float* __restrict__ bb) {
    int j = threadIdx.x;
    float mean = g_stats[j] * (1.f / NN);
    float var = g_stats[64 + j] * (1.f / NN) - mean * mean;
    float sc = bg[j] * rsqrtf(fmaxf(var, 0.f) + 1e-5f);
    g_scale[j] = sc;
    g_shift[j] = bb[j] - mean * sc;
}

// ---------------- h = softplus(h + agg*scale + shift) ----------------
__global__ void upd_k() {
    int i = blockIdx.x * 256 + threadIdx.x;
    if (i >= NN * 16) return;
    int j4 = (i & 15) * 4;
    float4 a = ((const float4*)g_agg)[i];
    float4 h = ((const float4*)g_h)[i];
    float4 sc = *(const float4*)(g_scale + j4);
    float4 sf = *(const float4*)(g_shift + j4);
    h.x = fsoftplus(fmaf(a.x, sc.x, h.x + sf.x));
    h.y = fsoftplus(fmaf(a.y, sc.y, h.y + sf.y));
    h.z = fsoftplus(fmaf(a.z, sc.z, h.z + sf.z));
    h.w = fsoftplus(fmaf(a.w, sc.w, h.w + sf.w));
    ((float4*)g_h)[i] = h;
}

// ---------------- pooling ----------------
__global__ void pool_k(const int* __restrict__ gi) {
    int i = blockIdx.x * 256 + threadIdx.x;
    if (i >= NN * 16) return;
    int n = i >> 4;
    int q = i & 15;
    int g = gi[n];
    float4 v = ((const float4*)g_h)[i];
    red_add_v4(g_pool + g * 64 + 4 * q, v.x, v.y, v.z, v.w);
    if (q == 0) red_add_f(&g_cnt[g], 1.f);
}

// ---------------- final MLP, one block per graph ----------------
__global__ void mlp_k(const float* __restrict__ w1, const float* __restrict__ b1,
                      const float* __restrict__ w2, const float* __restrict__ b2,
                      const float* __restrict__ w3, const float* __restrict__ b3,
                      float* __restrict__ out) {
    int b = blockIdx.x;
    int t = threadIdx.x;  // 128 threads
    __shared__ float pm[64];
    __shared__ float s1[128];
    __shared__ float s2[64];
    __shared__ float red[128];
    if (t < 64) {
        float c = g_cnt[b];
        c = (c < 1.f) ? 1.f : c;
        pm[t] = g_pool[b * 64 + t] / c;
    }
    __syncthreads();
    float a = b1[t];
#pragma unroll
    for (int k = 0; k < 64; k++) a = fmaf(pm[k], w1[k * 128 + t], a);
    s1[t] = fsoftplus(a);
    __syncthreads();
    if (t < 64) {
        float a2 = b2[t];
#pragma unroll
        for (int k = 0; k < 128; k++) a2 = fmaf(s1[k], w2[k * 64 + t], a2);
        s2[t] = fsoftplus(a2);
    }
    __syncthreads();
    float p = (t < 64) ? s2[t] * w3[t] : 0.f;
    red[t] = p;
    __syncthreads();
#pragma unroll
    for (int off = 64; off > 0; off >>= 1) {
        if (t < off) red[t] += red[t + off];
        __syncthreads();
    }
    if (t == 0) out[b] = red[0] + b3[0];
}

extern "C" void kernel_launch(void* const* d_in, const int* in_sizes, int n_in,
                              void* d_out, int out_size) {
    const float* nf  = (const float*)d_in[0];
    const int*   ei  = (const int*)d_in[1];
    const float* ef  = (const float*)d_in[2];
    const int*   gi  = (const int*)d_in[3];
    const float* ew  = (const float*)d_in[4];
    const float* eb  = (const float*)d_in[5];
    const float* gw  = (const float*)d_in[6];
    const float* gb  = (const float*)d_in[7];
    const float* cw  = (const float*)d_in[8];
    const float* cb  = (const float*)d_in[9];
    const float* bng = (const float*)d_in[10];
    const float* bnb = (const float*)d_in[11];
    const float* w1  = (const float*)d_in[12];
    const float* b1  = (const float*)d_in[13];
    const float* w2  = (const float*)d_in[14];
    const float* b2  = (const float*)d_in[15];
    const float* w3  = (const float*)d_in[16];
    const float* b3  = (const float*)d_in[17];
    float* out = (float*)d_out;
    const int* srcI = ei;
    const int* dstI = ei + EE;

    embed_k<<<(NN + 31) / 32, 256>>>(nf, ew, eb);
    for (int i = 0; i < 3; i++) {
        const float* gwi = gw + i * 138 * 64;
        const float* cwi = cw + i * 138 * 64;
        nodetf_k<<<(NN + 63) / 64, 256>>>(gwi, cwi, gb + i * 64, cb + i * 64);
        zero_agg_k<<<(NN * 16 + 255) / 256, 256>>>();
        edge_k<<<(EE + 255) / 256, 256>>>(srcI, dstI, ef, gwi + 128 * 64, cwi + 128 * 64);
        stats_k<<<512, 256>>>();
        bnfin_k<<<1, 64>>>(bng + i * 64, bnb + i * 64);
        upd_k<<<(NN * 16 + 255) / 256, 256>>>();
    }
    zero_pool_k<<<64, 256>>>();
    pool_k<<<(NN * 16 + 255) / 256, 256>>>(gi);
    mlp_k<<<BB, 128>>>(w1, b1, w2, b2, w3, b3, out);
}

// round 4
// speedup vs baseline: 3.9922x; 1.1588x over previous
#include <cuda_runtime.h>
#include <cuda_fp16.h>
#include <math.h>

// CGCNN on GB300. Ts/Td node tables stored fp16 (computed fp32), edge pass
// warp-per-edge with 40 weight regs, fp32 atomics aggregation, BN, pooling, MLP.

#define NN 100000
#define EE 1600000
#define BB 256
#define FN 35
#define FE 10

__device__ float g_h[NN * 64];
__device__ __half g_Tsh[NN * 128];
__device__ __half g_Tdh[NN * 128];
__device__ float g_agg[NN * 64];
__device__ float g_stats[128];
__device__ float g_scale[64];
__device__ float g_shift[64];
__device__ float g_pool[BB * 64];
__device__ float g_cnt[BB];

__device__ __forceinline__ float fsoftplus(float x) {
    return fmaxf(x, 0.f) + __logf(1.f + __expf(-fabsf(x)));
}
__device__ __forceinline__ float fsigmoid(float x) {
    return __fdividef(1.f, 1.f + __expf(-x));
}
__device__ __forceinline__ void red_add_v4(float* p, float a, float b, float c, float d) {
    asm volatile("red.global.add.v4.f32 [%0], {%1, %2, %3, %4};"
                 :: "l"(p), "f"(a), "f"(b), "f"(c), "f"(d) : "memory");
}
__device__ __forceinline__ void red_add_f(float* p, float v) {
    asm volatile("red.global.add.f32 [%0], %1;" :: "l"(p), "f"(v) : "memory");
}

// ---------------- embed: h = nf @ ew + eb, 32 nodes/block ----------------
__global__ __launch_bounds__(256) void embed_k(const float* __restrict__ nf,
                                               const float* __restrict__ ew,
                                               const float* __restrict__ eb) {
    __shared__ float sw[FN * 64];
    __shared__ float sb[64];
    __shared__ float snf[32][FN + 1];
    int tid = threadIdx.x;
    for (int i = tid; i < FN * 64; i += 256) sw[i] = ew[i];
    if (tid < 64) sb[tid] = eb[tid];
    int n0 = blockIdx.x * 32;
    for (int i = tid; i < 32 * FN; i += 256) {
        int r = i / FN, c = i % FN;
        int n = n0 + r;
        snf[r][c] = (n < NN) ? nf[(size_t)n * FN + c] : 0.f;
    }
    __syncthreads();
    int r = tid >> 6, j = tid & 63;
#pragma unroll
    for (int ii = 0; ii < 8; ii++) {
        int rr = r + ii * 4;
        int n = n0 + rr;
        if (n < NN) {
            float acc = sb[j];
#pragma unroll
            for (int k = 0; k < FN; k++) acc = fmaf(snf[rr][k], sw[k * 64 + j], acc);
            g_h[(size_t)n * 64 + j] = acc;
        }
    }
}

// ---------------- node transform -> fp16 tables ----------------
// 256 threads, thread owns one output column c (0..255); 64-node tiles.
__global__ __launch_bounds__(256) void nodetf_k(
    const float* __restrict__ gw, const float* __restrict__ cw,
    const float* __restrict__ gb, const float* __restrict__ cb) {
    __shared__ float4 hs4[64 * 16];  // 64 nodes x 64 feats
    int c = threadIdx.x;
    const float* wp;
    int cc;
    float bias = 0.f;
    if (c < 64)       { wp = gw;           cc = c; }
    else if (c < 128) { wp = cw;           cc = c - 64; }
    else if (c < 192) { wp = gw + 64 * 64; cc = c - 128; bias = gb[cc]; }
    else              { wp = cw + 64 * 64; cc = c - 192; bias = cb[cc]; }
    float w[64];
#pragma unroll
    for (int k = 0; k < 64; k++) w[k] = wp[k * 64 + cc];

    __half* outp = (c < 128) ? (g_Tsh + c) : (g_Tdh + (c - 128));

    int n0 = blockIdx.x * 64;
#pragma unroll
    for (int i = 0; i < 4; i++) {
        int idx = c + i * 256;
        int n = n0 + (idx >> 4);
        hs4[idx] = (n < NN) ? ((const float4*)g_h)[(size_t)n0 * 16 + idx]
                            : make_float4(0.f, 0.f, 0.f, 0.f);
    }
    __syncthreads();

#pragma unroll 1
    for (int j0 = 0; j0 < 64; j0 += 8) {
        float acc[8];
#pragma unroll
        for (int j = 0; j < 8; j++) acc[j] = bias;
#pragma unroll
        for (int k4 = 0; k4 < 16; k4++) {
#pragma unroll
            for (int j = 0; j < 8; j++) {
                float4 h = hs4[(j0 + j) * 16 + k4];
                acc[j] = fmaf(h.x, w[4 * k4 + 0], acc[j]);
                acc[j] = fmaf(h.y, w[4 * k4 + 1], acc[j]);
                acc[j] = fmaf(h.z, w[4 * k4 + 2], acc[j]);
                acc[j] = fmaf(h.w, w[4 * k4 + 3], acc[j]);
            }
        }
#pragma unroll
        for (int j = 0; j < 8; j++) {
            int n = n0 + j0 + j;
            if (n < NN) outp[(size_t)n * 128] = __float2half(acc[j]);
        }
    }
}

// ---------------- zero kernels ----------------
__global__ void zero_agg_k() {
    int i = blockIdx.x * 256 + threadIdx.x;
    if (i < NN * 16) ((float4*)g_agg)[i] = make_float4(0.f, 0.f, 0.f, 0.f);
    if (i < 128) g_stats[i] = 0.f;
}
__global__ void zero_pool_k() {
    int i = blockIdx.x * 256 + threadIdx.x;
    if (i < BB * 64) g_pool[i] = 0.f;
    if (i < BB) g_cnt[i] = 0.f;
}

// ---------------- edge pass: warp per edge, fp16 gathers ----------------
#define EPW 16  // edges per warp; block = 8 warps = 128 edges
__global__ __launch_bounds__(256, 3) void edge_k(
    const int* __restrict__ src, const int* __restrict__ dst,
    const float* __restrict__ ef,
    const float* __restrict__ gwE, const float* __restrict__ cwE) {
    int tid = threadIdx.x;
    int warp = tid >> 5;
    int l = tid & 31;

    float2 wg[FE], wc[FE];
#pragma unroll
    for (int k = 0; k < FE; k++) {
        wg[k] = *(const float2*)(gwE + k * 64 + 2 * l);
        wc[k] = *(const float2*)(cwE + k * 64 + 2 * l);
    }

    int base = blockIdx.x * (8 * EPW) + warp * EPW;

#pragma unroll 1
    for (int it = 0; it < EPW; it++) {
        int e = base + it;  // EE divisible by 128: no bounds check
        int s = __ldcs(&src[e]);
        int d = __ldcs(&dst[e]);
        const __half2* ts = (const __half2*)(g_Tsh + (size_t)s * 128);
        const __half2* td = (const __half2*)(g_Tdh + (size_t)d * 128);
        __half2 sg = ts[l];
        __half2 sc = ts[32 + l];
        __half2 dg = td[l];
        __half2 dc = td[32 + l];
        float2 a = __half22float2(sg), b = __half22float2(dg);
        float2 u = __half22float2(sc), v = __half22float2(dc);
        float x0 = a.x + b.x, x1 = a.y + b.y;
        float y0 = u.x + v.x, y1 = u.y + v.y;

        float evl = (l < FE) ? __ldcs(&ef[(size_t)e * FE + l]) : 0.f;
#pragma unroll
        for (int k = 0; k < FE; k++) {
            float ev = __shfl_sync(0xffffffffu, evl, k);
            x0 = fmaf(ev, wg[k].x, x0);
            x1 = fmaf(ev, wg[k].y, x1);
            y0 = fmaf(ev, wc[k].x, y0);
            y1 = fmaf(ev, wc[k].y, y1);
        }
        float m0 = fsigmoid(x0) * fsoftplus(y0);
        float m1 = fsigmoid(x1) * fsoftplus(y1);
        float p0 = __shfl_down_sync(0xffffffffu, m0, 1);
        float p1 = __shfl_down_sync(0xffffffffu, m1, 1);
        if ((l & 1) == 0)
            red_add_v4(g_agg + (size_t)s * 64 + 2 * l, m0, m1, p0, p1);
    }
}

// ---------------- BN stats ----------------
__global__ void stats_k() {
    int tid = threadIdx.x;
    int j = tid & 63;
    int r = tid >> 6;
    float s = 0.f, s2 = 0.f;
    for (int n = blockIdx.x * 4 + r; n < NN; n += gridDim.x * 4) {
        float v = g_agg[n * 64 + j];
        s += v;
        s2 += v * v;
    }
    __shared__ float sh[256], sh2[256];
    sh[tid] = s; sh2[tid] = s2;
    __syncthreads();
    if (tid < 64) {
        s = sh[tid] + sh[tid + 64] + sh[tid + 128] + sh[tid + 192];
        s2 = sh2[tid] + sh2[tid + 64] + sh2[tid + 128] + sh2[tid + 192];
        atomicAdd(&g_stats[tid], s);
        atomicAdd(&g_stats[64 + tid], s2);
    }
}

__global__ void bnfin_k(const float* __restrict__ bg, const float* __restrict__ bb) {
    int j = threadIdx.x;
    float mean = g_stats[j] * (1.f / NN);
    float var = g_stats[64 + j] * (1.f / NN) - mean * mean;
    float sc = bg[j] * rsqrtf(fmaxf(var, 0.f) + 1e-5f);
    g_scale[j] = sc;
    g_shift[j] = bb[j] - mean * sc;
}

// ---------------- h = softplus(h + agg*scale + shift) ----------------
__global__ void upd_k() {
    int i = blockIdx.x * 256 + threadIdx.x;
    if (i >= NN * 16) return;
    int j4 = (i & 15) * 4;
    float4 a = ((const float4*)g_agg)[i];
    float4 h = ((const float4*)g_h)[i];
    float4 sc = *(const float4*)(g_scale + j4);
    float4 sf = *(const float4*)(g_shift + j4);
    h.x = fsoftplus(fmaf(a.x, sc.x, h.x + sf.x));
    h.y = fsoftplus(fmaf(a.y, sc.y, h.y + sf.y));
    h.z = fsoftplus(fmaf(a.z, sc.z, h.z + sf.z));
    h.w = fsoftplus(fmaf(a.w, sc.w, h.w + sf.w));
    ((float4*)g_h)[i] = h;
}

// ---------------- pooling ----------------
__global__ void pool_k(const int* __restrict__ gi) {
    int i = blockIdx.x * 256 + threadIdx.x;
    if (i >= NN * 16) return;
    int n = i >> 4;
    int q = i & 15;
    int g = gi[n];
    float4 v = ((const float4*)g_h)[i];
    red_add_v4(g_pool + g * 64 + 4 * q, v.x, v.y, v.z, v.w);
    if (q == 0) red_add_f(&g_cnt[g], 1.f);
}

// ---------------- final MLP, one block per graph ----------------
__global__ void mlp_k(const float* __restrict__ w1, const float* __restrict__ b1,
                      const float* __restrict__ w2, const float* __restrict__ b2,
                      const float* __restrict__ w3, const float* __restrict__ b3,
                      float* __restrict__ out) {
    int b = blockIdx.x;
    int t = threadIdx.x;  // 128 threads
    __shared__ float pm[64];
    __shared__ float s1[128];
    __shared__ float s2[64];
    __shared__ float red[128];
    if (t < 64) {
        float c = g_cnt[b];
        c = (c < 1.f) ? 1.f : c;
        pm[t] = g_pool[b * 64 + t] / c;
    }
    __syncthreads();
    float a = b1[t];
#pragma unroll
    for (int k = 0; k < 64; k++) a = fmaf(pm[k], w1[k * 128 + t], a);
    s1[t] = fsoftplus(a);
    __syncthreads();
    if (t < 64) {
        float a2 = b2[t];
#pragma unroll
        for (int k = 0; k < 128; k++) a2 = fmaf(s1[k], w2[k * 64 + t], a2);
        s2[t] = fsoftplus(a2);
    }
    __syncthreads();
    float p = (t < 64) ? s2[t] * w3[t] : 0.f;
    red[t] = p;
    __syncthreads();
#pragma unroll
    for (int off = 64; off > 0; off >>= 1) {
        if (t < off) red[t] += red[t + off];
        __syncthreads();
    }
    if (t == 0) out[b] = red[0] + b3[0];
}

extern "C" void kernel_launch(void* const* d_in, const int* in_sizes, int n_in,
                              void* d_out, int out_size) {
    const float* nf  = (const float*)d_in[0];
    const int*   ei  = (const int*)d_in[1];
    const float* ef  = (const float*)d_in[2];
    const int*   gi  = (const int*)d_in[3];
    const float* ew  = (const float*)d_in[4];
    const float* eb  = (const float*)d_in[5];
    const float* gw  = (const float*)d_in[6];
    const float* gb  = (const float*)d_in[7];
    const float* cw  = (const float*)d_in[8];
    const float* cb  = (const float*)d_in[9];
    const float* bng = (const float*)d_in[10];
    const float* bnb = (const float*)d_in[11];
    const float* w1  = (const float*)d_in[12];
    const float* b1  = (const float*)d_in[13];
    const float* w2  = (const float*)d_in[14];
    const float* b2  = (const float*)d_in[15];
    const float* w3  = (const float*)d_in[16];
    const float* b3  = (const float*)d_in[17];
    float* out = (float*)d_out;
    const int* srcI = ei;
    const int* dstI = ei + EE;

    embed_k<<<(NN + 31) / 32, 256>>>(nf, ew, eb);
    for (int i = 0; i < 3; i++) {
        const float* gwi = gw + i * 138 * 64;
        const float* cwi = cw + i * 138 * 64;
        nodetf_k<<<(NN + 63) / 64, 256>>>(gwi, cwi, gb + i * 64, cb + i * 64);
        zero_agg_k<<<(NN * 16 + 255) / 256, 256>>>();
        edge_k<<<EE / 128, 256>>>(srcI, dstI, ef, gwi + 128 * 64, cwi + 128 * 64);
        stats_k<<<512, 256>>>();
        bnfin_k<<<1, 64>>>(bng + i * 64, bnb + i * 64);
        upd_k<<<(NN * 16 + 255) / 256, 256>>>();
    }
    zero_pool_k<<<64, 256>>>();
    pool_k<<<(NN * 16 + 255) / 256, 256>>>(gi);
    mlp_k<<<BB, 128>>>(w1, b1, w2, b2, w3, b3, out);
}